// round 15
// baseline (speedup 1.0000x reference)
#include <cuda_runtime.h>
#include <cuda_bf16.h>

#define H      488
#define AW     484          // H - 5 + 1
#define KCL    6
#define NB     32
#define ITERS  10
#define SEG    121          // 484 = 4 * 121 windows per row
#define NSEG   4
#define NPART  (AW * NSEG)  // 1936 partials per batch
#define CR0    8            // rows per scan0 chunk
#define NCH0   61           // ceil(484/8)
#define NE4    (H * H / 4)  // 59536 uint4/float4 per batch
#define NCHE   8            // eq chunks per batch
#define CE4    7442         // NE4 / 8
#define RW     5            // warps per cluster in refine (30 of 32 warps)

// Scratch (allocation-free: __device__ globals) — NO colsum array anymore
__device__ float g_pv[NB * NPART];          // per-(row,seg) argmax value
__device__ int   g_pi[NB * NPART];          // per-(row,seg) argmax flat window idx
__device__ int   g_wr[NB * KCL], g_wc[NB * KCL];
__device__ float g_mv[NB * KCL];
__device__ int   g_eq[NB * KCL];            // first-occurrence flat index

__device__ __forceinline__ void better(float v, int i, float& bv, int& bi) {
    if (v > bv || (v == bv && i < bi)) { bv = v; bi = i; }
}

// ---------------------------------------------------------------------------
// scan0: input -> initial argmax partials. colsum lives ONLY in smem
// (the global array was 30 MB of writes for ~8 KB of reads).
// grid (NB, 61) x 128. 8 rows per chunk, 4 cols per thread (vectorized).
// ---------------------------------------------------------------------------
__global__ __launch_bounds__(128)
void scan0_kernel(const float* __restrict__ in) {
    const int b = blockIdx.x, cb = blockIdx.y, tid = threadIdx.x;
    const float* src = in + (size_t)b * H * H;

    __shared__ float s_cs[CR0][H];

    const int R0 = CR0 * cb, R1 = min(AW, R0 + CR0);

    // column 5-sums, 4 columns per thread via float4 (left-assoc per column)
    if (tid < H / 4) {
        const float4* s4 = (const float4*)src;
        const int HQ = H / 4;                 // 122 float4 per row
        float4 w0 = s4[(R0 + 0) * HQ + tid], w1 = s4[(R0 + 1) * HQ + tid],
               w2 = s4[(R0 + 2) * HQ + tid], w3 = s4[(R0 + 3) * HQ + tid], w4;
        for (int i = R0; i < R1; i++) {
            w4 = s4[(i + 4) * HQ + tid];
            float4 s;
            s.x = w0.x + w1.x + w2.x + w3.x + w4.x;
            s.y = w0.y + w1.y + w2.y + w3.y + w4.y;
            s.z = w0.z + w1.z + w2.z + w3.z + w4.z;
            s.w = w0.w + w1.w + w2.w + w3.w + w4.w;
            *(float4*)&s_cs[i - R0][tid * 4] = s;
            w0 = w1; w1 = w2; w2 = w3; w3 = w4;
        }
    }
    __syncthreads();

    // partials: up to 32 (row,seg) pairs, 4 sub-threads each
    const int pair = tid >> 2, sub = tid & 3;
    const int lr = pair >> 2, sg = pair & 3;
    const int nrows = R1 - R0;

    float bv = -1.0f; int bi = 0x7fffffff;
    if (lr < nrows) {
        const float* row = s_cs[lr];
        const int jbeg = sg * SEG;
        for (int j = jbeg + sub; j < jbeg + SEG; j += 4) {
            float v = row[j] + row[j + 1] + row[j + 2] + row[j + 3] + row[j + 4];
            better(v, (R0 + lr) * AW + j, bv, bi);
        }
    }
    #pragma unroll
    for (int off = 2; off; off >>= 1) {
        float ov = __shfl_down_sync(0xffffffffu, bv, off);
        int   oi = __shfl_down_sync(0xffffffffu, bi, off);
        better(ov, oi, bv, bi);
    }
    if (sub == 0 && lr < nrows) {
        g_pv[b * NPART + (R0 + lr) * NSEG + sg] = bv;
        g_pi[b * NPART + (R0 + lr) * NSEG + sg] = bi;
    }
}

// ---------------------------------------------------------------------------
// greedy6: 6 greedy extractions per batch. grid NB x 512.
// Lazy D: a partial changes ONLY if its argmax col is in [c-4, c+4]
// (box sums only decrease). D recomputes the affected segments' colsum
// directly from src (coverage zeroing, same left-assoc order -> bit-exact),
// so no global colsum array / repair phase exists.
// ---------------------------------------------------------------------------
__global__ __launch_bounds__(512)
void greedy6_kernel(const float* __restrict__ in) {
    const int b = blockIdx.x, tid = threadIdx.x;
    const int warp = tid >> 5, lane = tid & 31;
    const float* src = in + (size_t)b * H * H;

    __shared__ float s_pv[NPART];
    __shared__ int   s_pi[NPART];
    __shared__ float s_rv[16];
    __shared__ int   s_ri[16];
    __shared__ int   s_wr[KCL], s_wc[KCL];
    __shared__ float s_mv[KCL];
    __shared__ int   s_r, s_c;
    __shared__ float s_csbuf[16][SEG + 4];   // per-warp colsum segment scratch

    for (int i = tid; i < NPART; i += 512) {
        s_pv[i] = g_pv[b * NPART + i];
        s_pi[i] = g_pi[b * NPART + i];
    }
    if (tid < KCL) g_eq[b * KCL + tid] = 0x7fffffff;
    __syncthreads();

    for (int it = 0; it < KCL; it++) {
        // A: argmax over 1936 smem partials (two-level shuffle tree)
        {
            float bv = -1.0f; int bi = 0x7fffffff;
            for (int i = tid; i < NPART; i += 512) better(s_pv[i], s_pi[i], bv, bi);
            #pragma unroll
            for (int off = 16; off; off >>= 1) {
                float ov = __shfl_down_sync(0xffffffffu, bv, off);
                int   oi = __shfl_down_sync(0xffffffffu, bi, off);
                better(ov, oi, bv, bi);
            }
            if (lane == 0) { s_rv[warp] = bv; s_ri[warp] = bi; }
        }
        __syncthreads();
        if (warp == 0) {
            float bv = (lane < 16) ? s_rv[lane] : -1.0f;
            int   bi = (lane < 16) ? s_ri[lane] : 0x7fffffff;
            #pragma unroll
            for (int off = 8; off; off >>= 1) {
                float ov = __shfl_down_sync(0xffffffffu, bv, off);
                int   oi = __shfl_down_sync(0xffffffffu, bi, off);
                better(ov, oi, bv, bi);
            }
            if (lane == 0) { s_r = bi / AW; s_c = bi % AW; }
        }
        __syncthreads();
        const int r = s_r, c = s_c;
        const int r0c = max(0, r - 4), r1c = min(AW - 1, r + 4);

        if (warp == 0) {
            // B: window max on warp 0 (value = orig unless covered earlier)
            float v = -1.0f;
            if (lane < 25) {
                int y = r + lane / 5, x = c + lane % 5;
                v = src[y * H + x];
                for (int j = 0; j < it; j++)
                    if ((unsigned)(y - s_wr[j]) < 5u && (unsigned)(x - s_wc[j]) < 5u) v = 0.0f;
            }
            #pragma unroll
            for (int off = 16; off; off >>= 1)
                v = fmaxf(v, __shfl_down_sync(0xffffffffu, v, off));
            if (lane == 0) { s_mv[it] = v; s_wr[it] = r; s_wc[it] = c; }
        }
        __syncthreads();   // s_wr[it]/s_wc[it] visible before D's coverage

        // D: lazy recompute — only partials whose stored argmax window
        // overlaps the zeroed columns can change. Colsum rebuilt from src
        // with coverage over windows j <= it (left-assoc, bit-exact).
        {
            const int jlo = max(0, c - 4), jhi = min(AW - 1, c + 4);
            const int s0 = jlo / SEG, s1 = jhi / SEG;
            const int nsegs = s1 - s0 + 1;
            const int npairs = (r1c - r0c + 1) * nsegs;
            for (int p = warp; p < npairs; p += 16) {
                const int rr = r0c + p / nsegs, sg = s0 + p % nsegs;
                const int ocol = s_pi[rr * NSEG + sg] - rr * AW;
                if (ocol < jlo || ocol > jhi) continue;      // provably unchanged
                const int c0 = sg * SEG;
                // rebuild colsum for cols [c0, c0+SEG+4)
                for (int j = lane; j < SEG + 4; j += 32) {
                    const int cc = c0 + j;
                    float s = 0.0f;
                    #pragma unroll
                    for (int d = 0; d < 5; d++) {
                        const int y = rr + d;
                        float v = src[y * H + cc];
                        for (int jj = 0; jj <= it; jj++)
                            if ((unsigned)(y - s_wr[jj]) < 5u &&
                                (unsigned)(cc - s_wc[jj]) < 5u) v = 0.0f;
                        s = s + v;   // left-assoc, matches scan0 ring
                    }
                    s_csbuf[warp][j] = s;
                }
                __syncwarp();
                const float* rb = s_csbuf[warp];
                float bv2 = -1.0f; int bi2 = 0x7fffffff;
                for (int j = lane; j < SEG; j += 32) {
                    float v = rb[j] + rb[j + 1] + rb[j + 2] + rb[j + 3] + rb[j + 4];
                    better(v, rr * AW + c0 + j, bv2, bi2);
                }
                #pragma unroll
                for (int off = 16; off; off >>= 1) {
                    float ov = __shfl_down_sync(0xffffffffu, bv2, off);
                    int   oi = __shfl_down_sync(0xffffffffu, bi2, off);
                    better(ov, oi, bv2, bi2);
                }
                if (lane == 0) { s_pv[rr * NSEG + sg] = bv2; s_pi[rr * NSEG + sg] = bi2; }
                __syncwarp();
            }
        }
        __syncthreads();
    }

    if (tid < KCL) {
        g_wr[b * KCL + tid] = s_wr[tid];
        g_wc[b * KCL + tid] = s_wc[tid];
        g_mv[b * KCL + tid] = s_mv[tid];
    }
}

// ---------------------------------------------------------------------------
// eq: first-occurrence scan, grid (NB, 8) x 256 — full chip. Branchless
// exact-bit filter, 4-way unrolled loads for MLP. Global atomicMin.
// ---------------------------------------------------------------------------
__global__ __launch_bounds__(256)
void eq_kernel(const float* __restrict__ in) {
    const int b = blockIdx.x, cb = blockIdx.y, tid = threadIdx.x;

    __shared__ unsigned s_p[KCL];
    __shared__ int      s_wr[KCL], s_wc[KCL];

    if (tid < KCL) {
        s_p[tid]  = __float_as_uint(g_mv[b * KCL + tid]);
        s_wr[tid] = g_wr[b * KCL + tid];
        s_wc[tid] = g_wc[b * KCL + tid];
    }
    __syncthreads();
    const unsigned p0 = s_p[0], p1 = s_p[1], p2 = s_p[2],
                   p3 = s_p[3], p4 = s_p[4], p5 = s_p[5];

    const uint4* h4 = (const uint4*)(in + (size_t)b * H * H);
    const int b0 = cb * CE4, e0 = min(NE4, b0 + CE4);

    for (int tt = b0 + tid; tt < e0; tt += 256 * 4) {
        uint4 v[4];
        bool ok[4];
        #pragma unroll
        for (int q = 0; q < 4; q++) {
            int idx = tt + q * 256;
            ok[q] = idx < e0;
            v[q] = ok[q] ? h4[idx] : make_uint4(0u, 0u, 0u, 0u);
        }
        bool hit = false;
        #pragma unroll
        for (int q = 0; q < 4; q++) {
            hit = hit |
                (v[q].x == p0) | (v[q].y == p0) | (v[q].z == p0) | (v[q].w == p0) |
                (v[q].x == p1) | (v[q].y == p1) | (v[q].z == p1) | (v[q].w == p1) |
                (v[q].x == p2) | (v[q].y == p2) | (v[q].z == p2) | (v[q].w == p2) |
                (v[q].x == p3) | (v[q].y == p3) | (v[q].z == p3) | (v[q].w == p3) |
                (v[q].x == p4) | (v[q].y == p4) | (v[q].z == p4) | (v[q].w == p4) |
                (v[q].x == p5) | (v[q].y == p5) | (v[q].z == p5) | (v[q].w == p5);
        }
        if (!hit) continue;   // taken almost never (exact-bit matches only)
        #pragma unroll
        for (int q = 0; q < 4; q++) {
            if (!ok[q]) continue;
            #pragma unroll
            for (int u = 0; u < 4; u++) {
                unsigned val = (u == 0) ? v[q].x : (u == 1) ? v[q].y
                             : (u == 2) ? v[q].z : v[q].w;
                int id = (tt + q * 256) * 4 + u;
                #pragma unroll
                for (int i = 0; i < KCL; i++) {
                    unsigned pp = (i == 0) ? p0 : (i == 1) ? p1 : (i == 2) ? p2
                                : (i == 3) ? p3 : (i == 4) ? p4 : p5;
                    if (val == pp) {
                        int y = id / H, x = id - y * H;
                        bool cov = false;
                        for (int j = 0; j < i; j++)
                            if ((unsigned)(y - s_wr[j]) < 5u && (unsigned)(x - s_wc[j]) < 5u) cov = true;
                        if (!cov) atomicMin(&g_eq[b * KCL + i], id);
                    }
                }
            }
        }
    }
}

// ---------------------------------------------------------------------------
// refine (R10-proven): 10 mean-shift iterations, 5 warps/cluster, one block
// per batch. rsqrtf + __fdividef, x-invariants hoisted, eps-clamp hoisted
// (exact identity). Centers updated by 6 threads (2 barriers/iter).
// ---------------------------------------------------------------------------
__global__ __launch_bounds__(1024)
void refine_kernel(const float* __restrict__ in, float* __restrict__ out) {
    const int b = blockIdx.x, tid = threadIdx.x;
    const int warp = tid >> 5, lane = tid & 31;
    const float* src = in + (size_t)b * H * H;

    __shared__ float pY[KCL][RW], pX[KCL][RW], pW[KCL][RW];
    __shared__ float s_cy[KCL], s_cx[KCL];

    if (tid < KCL) {
        int fh = g_eq[b * KCL + tid];
        s_cy[tid] = (float)(fh / H);
        s_cx[tid] = (float)(fh % H);
    }
    __syncthreads();

    const int k = warp / RW;            // 0..5 for warps 0..29; warps 30,31 idle
    const int sw = warp - k * RW;
    const bool active = (warp < KCL * RW);

    for (int it = 0; it < ITERS; it++) {
        if (active) {
            // all 6 centers -> registers (constant smem indices, no spill)
            float rcy[KCL], rcx[KCL];
            #pragma unroll
            for (int i = 0; i < KCL; i++) { rcy[i] = s_cy[i]; rcx[i] = s_cx[i]; }

            float cy = rcy[0], cx = rcx[0];
            if (k == 1) { cy = rcy[1]; cx = rcx[1]; }
            if (k == 2) { cy = rcy[2]; cx = rcx[2]; }
            if (k == 3) { cy = rcy[3]; cx = rcx[3]; }
            if (k == 4) { cy = rcy[4]; cx = rcx[4]; }
            if (k == 5) { cy = rcy[5]; cx = rcx[5]; }

            const int y0 = max(0, (int)floorf(cy - 12.0f));
            const int y1 = min(H - 1, (int)ceilf(cy + 12.0f));
            const int x0 = max(0, (int)floorf(cx - 12.0f));
            const int x1 = min(H - 1, (int)ceilf(cx + 12.0f));
            const int w  = x1 - x0 + 1;        // <= 26 <= 32 lanes

            float sy = 0.0f, sx = 0.0f, swt = 0.0f;
            const int x = x0 + lane;
            if (lane < w) {
                const float fx = (float)x;
                const float dx2 = (fx - cx) * (fx - cx);
                float ex2[KCL];
                #pragma unroll
                for (int i = 0; i < KCL; i++) {
                    float ex = fx - rcx[i];
                    ex2[i] = ex * ex;
                }
                for (int y = y0 + sw; y <= y1; y += RW) {
                    const float fy = (float)y;
                    const float dy = fy - cy;
                    const float d2r = fmaf(dy, dy, dx2);
                    if (d2r < 144.0f) {
                        float mr = d2r;
                        #pragma unroll
                        for (int k2 = 0; k2 < KCL; k2++) {
                            float ey = fy - rcy[k2];
                            mr = fminf(mr, fmaf(ey, ey, ex2[k2]));
                        }
                        const float d2 = fmaxf(d2r, 1e-6f);
                        const float m2 = fmaxf(mr,  1e-6f);
                        float s = m2 * rsqrtf(m2);               // ~sqrt(m2)
                        float wgt = __fdividef(src[y * H + x] * s, d2);
                        sy = fmaf(wgt, fy, sy);
                        sx = fmaf(wgt, fx, sx);
                        swt += wgt;
                    }
                }
            }
            #pragma unroll
            for (int off = 16; off; off >>= 1) {
                sy  += __shfl_down_sync(0xffffffffu, sy, off);
                sx  += __shfl_down_sync(0xffffffffu, sx, off);
                swt += __shfl_down_sync(0xffffffffu, swt, off);
            }
            if (lane == 0) { pY[k][sw] = sy; pX[k][sw] = sx; pW[k][sw] = swt; }
        }
        __syncthreads();
        // 6 threads update centers (12 MUFU total per iteration)
        if (tid < KCL) {
            float ay = pY[tid][0] + pY[tid][1] + pY[tid][2] + pY[tid][3] + pY[tid][4];
            float ax = pX[tid][0] + pX[tid][1] + pX[tid][2] + pX[tid][3] + pX[tid][4];
            float aw = pW[tid][0] + pW[tid][1] + pW[tid][2] + pW[tid][3] + pW[tid][4];
            s_cy[tid] = __fdividef(ay, aw);
            s_cx[tid] = __fdividef(ax, aw);
        }
        __syncthreads();
    }

    if (tid < KCL) {
        float fy = s_cy[tid], fx = s_cx[tid];
        int iy = (int)rintf(fy);   // round-half-to-even == jnp.round
        int ix = (int)rintf(fx);
        out[(b * KCL + tid) * 2 + 0] = (float)iy;
        out[(b * KCL + tid) * 2 + 1] = (float)ix;
        int sy0 = min(max(iy - 2, 0), H - 4);   // dynamic_slice clamp
        int sx0 = min(max(ix - 2, 0), H - 4);
        float cf = 0.0f;
        #pragma unroll
        for (int di = 0; di < 4; di++)
            #pragma unroll
            for (int dj = 0; dj < 4; dj++)
                cf += src[(sy0 + di) * H + (sx0 + dj)];
        out[NB * KCL * 2 + b * KCL + tid] = cf;
    }
}

extern "C" void kernel_launch(void* const* d_in, const int* in_sizes, int n_in,
                              void* d_out, int out_size) {
    const float* hm = (const float*)d_in[0];
    float* out = (float*)d_out;

    scan0_kernel<<<dim3(NB, NCH0), 128>>>(hm);
    greedy6_kernel<<<NB, 512>>>(hm);
    eq_kernel<<<dim3(NB, NCHE), 256>>>(hm);
    refine_kernel<<<NB, 1024>>>(hm, out);
}

// round 16
// speedup vs baseline: 1.1550x; 1.1550x over previous
#include <cuda_runtime.h>
#include <cuda_bf16.h>

#define H      488
#define AW     484          // H - 5 + 1
#define KCL    6
#define NB     32
#define ITERS  10
#define SEG    121          // 484 = 4 * 121 windows per row
#define NSEG   4
#define NPART  (AW * NSEG)  // 1936 partials per batch
#define CR0    8            // rows per scan0 chunk
#define NCH0   61           // ceil(484/8)
#define NE4    (H * H / 4)  // 59536 uint4/float4 per batch
#define RW     5            // warps per cluster in refine (30 of 32 warps)

// Scratch (allocation-free: __device__ globals)
__device__ float g_colsum[NB * AW * H];     // vertical 5-sums
__device__ float g_pv[NB * NPART];          // per-(row,seg) argmax value
__device__ int   g_pi[NB * NPART];          // per-(row,seg) argmax flat window idx
__device__ int   g_wr[NB * KCL], g_wc[NB * KCL];
__device__ float g_mv[NB * KCL];

__device__ __forceinline__ void better(float v, int i, float& bv, int& bi) {
    if (v > bv || (v == bv && i < bi)) { bv = v; bi = i; }
}

// ---------------------------------------------------------------------------
// scan0: input -> colsum (global, float4) + initial argmax partials.
// grid (NB, 61) x 128. 8 rows per chunk, 4 cols per thread (vectorized).
// ---------------------------------------------------------------------------
__global__ __launch_bounds__(128)
void scan0_kernel(const float* __restrict__ in) {
    const int b = blockIdx.x, cb = blockIdx.y, tid = threadIdx.x;
    const float* src = in + (size_t)b * H * H;
    float* cs = g_colsum + (size_t)b * AW * H;

    __shared__ float s_cs[CR0][H];

    const int R0 = CR0 * cb, R1 = min(AW, R0 + CR0);

    // column 5-sums, 4 columns per thread via float4 (left-assoc per column)
    if (tid < H / 4) {
        const float4* s4 = (const float4*)src;
        float4* c4 = (float4*)cs;
        const int HQ = H / 4;                 // 122 float4 per row
        float4 w0 = s4[(R0 + 0) * HQ + tid], w1 = s4[(R0 + 1) * HQ + tid],
               w2 = s4[(R0 + 2) * HQ + tid], w3 = s4[(R0 + 3) * HQ + tid], w4;
        for (int i = R0; i < R1; i++) {
            w4 = s4[(i + 4) * HQ + tid];
            float4 s;
            s.x = w0.x + w1.x + w2.x + w3.x + w4.x;
            s.y = w0.y + w1.y + w2.y + w3.y + w4.y;
            s.z = w0.z + w1.z + w2.z + w3.z + w4.z;
            s.w = w0.w + w1.w + w2.w + w3.w + w4.w;
            *(float4*)&s_cs[i - R0][tid * 4] = s;
            c4[i * HQ + tid] = s;
            w0 = w1; w1 = w2; w2 = w3; w3 = w4;
        }
    }
    __syncthreads();

    // partials: up to 32 (row,seg) pairs, 4 sub-threads each
    const int pair = tid >> 2, sub = tid & 3;
    const int lr = pair >> 2, sg = pair & 3;
    const int nrows = R1 - R0;

    float bv = -1.0f; int bi = 0x7fffffff;
    if (lr < nrows) {
        const float* row = s_cs[lr];
        const int jbeg = sg * SEG;
        for (int j = jbeg + sub; j < jbeg + SEG; j += 4) {
            float v = row[j] + row[j + 1] + row[j + 2] + row[j + 3] + row[j + 4];
            better(v, (R0 + lr) * AW + j, bv, bi);
        }
    }
    #pragma unroll
    for (int off = 2; off; off >>= 1) {
        float ov = __shfl_down_sync(0xffffffffu, bv, off);
        int   oi = __shfl_down_sync(0xffffffffu, bi, off);
        better(ov, oi, bv, bi);
    }
    if (sub == 0 && lr < nrows) {
        g_pv[b * NPART + (R0 + lr) * NSEG + sg] = bv;
        g_pi[b * NPART + (R0 + lr) * NSEG + sg] = bi;
    }
}

// ---------------------------------------------------------------------------
// greedy6: 6 greedy extractions per batch. grid NB x 1024.
// Incremental colsum repair (<=45 entries) in global; lazy D (a partial
// changes only if its stored argmax col is in [c-4, c+4] — sums only
// decrease, so others are provably unchanged).
// ---------------------------------------------------------------------------
__global__ __launch_bounds__(1024)
void greedy6_kernel(const float* __restrict__ in) {
    const int b = blockIdx.x, tid = threadIdx.x;
    const int warp = tid >> 5, lane = tid & 31;
    const float* src = in + (size_t)b * H * H;
    float* cs = g_colsum + (size_t)b * AW * H;

    __shared__ float s_pv[NPART];
    __shared__ int   s_pi[NPART];
    __shared__ float s_rv[32];
    __shared__ int   s_ri[32];
    __shared__ int   s_wr[KCL], s_wc[KCL];
    __shared__ float s_mv[KCL];
    __shared__ int   s_r, s_c;

    for (int i = tid; i < NPART; i += 1024) {
        s_pv[i] = g_pv[b * NPART + i];
        s_pi[i] = g_pi[b * NPART + i];
    }
    __syncthreads();

    for (int it = 0; it < KCL; it++) {
        // A: argmax over 1936 smem partials (two-level shuffle tree)
        {
            float bv = -1.0f; int bi = 0x7fffffff;
            for (int i = tid; i < NPART; i += 1024) better(s_pv[i], s_pi[i], bv, bi);
            #pragma unroll
            for (int off = 16; off; off >>= 1) {
                float ov = __shfl_down_sync(0xffffffffu, bv, off);
                int   oi = __shfl_down_sync(0xffffffffu, bi, off);
                better(ov, oi, bv, bi);
            }
            if (lane == 0) { s_rv[warp] = bv; s_ri[warp] = bi; }
        }
        __syncthreads();
        if (warp == 0) {
            float bv = s_rv[lane]; int bi = s_ri[lane];
            #pragma unroll
            for (int off = 16; off; off >>= 1) {
                float ov = __shfl_down_sync(0xffffffffu, bv, off);
                int   oi = __shfl_down_sync(0xffffffffu, bi, off);
                better(ov, oi, bv, bi);
            }
            if (lane == 0) { s_r = bi / AW; s_c = bi % AW; }
        }
        __syncthreads();
        const int r = s_r, c = s_c;
        const int r0c = max(0, r - 4), r1c = min(AW - 1, r + 4);

        if (warp == 0) {
            // B: window max on warp 0 (value = orig unless covered earlier)
            float v = -1.0f;
            if (lane < 25) {
                int y = r + lane / 5, x = c + lane % 5;
                v = src[y * H + x];
                for (int j = 0; j < it; j++)
                    if ((unsigned)(y - s_wr[j]) < 5u && (unsigned)(x - s_wc[j]) < 5u) v = 0.0f;
            }
            #pragma unroll
            for (int off = 16; off; off >>= 1)
                v = fmaxf(v, __shfl_down_sync(0xffffffffu, v, off));
            if (lane == 0) { s_mv[it] = v; s_wr[it] = r; s_wc[it] = c; }
        } else {
            // C (warps 1+): incremental colsum repair (<=45 entries)
            int nc = (r1c - r0c + 1) * 5;
            int idx = tid - 32;
            if (idx < nc) {
                int rr = r0c + idx / 5, cc = c + idx % 5;
                float s = 0.0f;
                #pragma unroll
                for (int d = 0; d < 5; d++) {
                    int y = rr + d;
                    float v = src[y * H + cc];
                    if ((unsigned)(y - r) < 5u && (unsigned)(cc - c) < 5u) v = 0.0f;
                    for (int j = 0; j < it; j++)
                        if ((unsigned)(y - s_wr[j]) < 5u && (unsigned)(cc - s_wc[j]) < 5u) v = 0.0f;
                    s = s + v;   // left-assoc, matches scan0 ring
                }
                cs[rr * H + cc] = s;
            }
        }
        __syncthreads();

        // D: lazy recompute — only partials whose stored argmax window
        // overlaps the zeroed columns can change (sums only decrease).
        {
            const int jlo = max(0, c - 4), jhi = min(AW - 1, c + 4);
            const int s0 = jlo / SEG, s1 = jhi / SEG;
            const int nsegs = s1 - s0 + 1;
            const int npairs = (r1c - r0c + 1) * nsegs;
            for (int p = warp; p < npairs; p += 32) {
                int rr = r0c + p / nsegs, sg = s0 + p % nsegs;
                int ocol = s_pi[rr * NSEG + sg] - rr * AW;   // argmax window col
                if (ocol < jlo || ocol > jhi) continue;      // provably unchanged
                const float* row = cs + rr * H;
                float bv2 = -1.0f; int bi2 = 0x7fffffff;
                for (int j = sg * SEG + lane; j < sg * SEG + SEG; j += 32) {
                    float v = row[j] + row[j + 1] + row[j + 2] + row[j + 3] + row[j + 4];
                    better(v, rr * AW + j, bv2, bi2);
                }
                #pragma unroll
                for (int off = 16; off; off >>= 1) {
                    float ov = __shfl_down_sync(0xffffffffu, bv2, off);
                    int   oi = __shfl_down_sync(0xffffffffu, bi2, off);
                    better(ov, oi, bv2, bi2);
                }
                if (lane == 0) { s_pv[rr * NSEG + sg] = bv2; s_pi[rr * NSEG + sg] = bi2; }
            }
        }
        __syncthreads();
    }

    if (tid < KCL) {
        g_wr[b * KCL + tid] = s_wr[tid];
        g_wc[b * KCL + tid] = s_wc[tid];
        g_mv[b * KCL + tid] = s_mv[tid];
    }
}

// ---------------------------------------------------------------------------
// refine: fused per-batch pipeline, grid NB x 1024.
//   (II)  eq prologue: branchless exact-bit first-occurrence scan of this
//         batch for all 6 maxima (coverage -> 0, never equal); shared
//         atomicMin (commutative -> deterministic); 4-way unrolled loads.
//   (III) 10 mean-shift iterations (R10-proven: 5 warps/cluster, rsqrtf +
//         __fdividef, hoisted invariants, 6-thread center update).
//   (IV)  round + clamped 4x4 confidence windows on the ORIGINAL heatmap.
// ---------------------------------------------------------------------------
__global__ __launch_bounds__(1024)
void refine_kernel(const float* __restrict__ in, float* __restrict__ out) {
    const int b = blockIdx.x, tid = threadIdx.x;
    const int warp = tid >> 5, lane = tid & 31;
    const float* src = in + (size_t)b * H * H;

    __shared__ float pY[KCL][RW], pX[KCL][RW], pW[KCL][RW];
    __shared__ float s_cy[KCL], s_cx[KCL];
    __shared__ unsigned s_p[KCL];
    __shared__ int   s_wr[KCL], s_wc[KCL];
    __shared__ int   s_eq[KCL];

    if (tid < KCL) {
        s_p[tid]  = __float_as_uint(g_mv[b * KCL + tid]);
        s_wr[tid] = g_wr[b * KCL + tid];
        s_wc[tid] = g_wc[b * KCL + tid];
        s_eq[tid] = 0x7fffffff;
    }
    __syncthreads();

    // ---- (II) eq scan over this batch's image
    {
        const unsigned p0 = s_p[0], p1 = s_p[1], p2 = s_p[2],
                       p3 = s_p[3], p4 = s_p[4], p5 = s_p[5];
        const uint4* h4 = (const uint4*)src;
        for (int tt = tid; tt < NE4; tt += 1024 * 4) {
            uint4 v[4];
            bool ok[4];
            #pragma unroll
            for (int q = 0; q < 4; q++) {
                int idx = tt + q * 1024;
                ok[q] = idx < NE4;
                v[q] = ok[q] ? h4[idx] : make_uint4(0u, 0u, 0u, 0u);
            }
            bool hit = false;
            #pragma unroll
            for (int q = 0; q < 4; q++) {
                hit = hit |
                    (v[q].x == p0) | (v[q].y == p0) | (v[q].z == p0) | (v[q].w == p0) |
                    (v[q].x == p1) | (v[q].y == p1) | (v[q].z == p1) | (v[q].w == p1) |
                    (v[q].x == p2) | (v[q].y == p2) | (v[q].z == p2) | (v[q].w == p2) |
                    (v[q].x == p3) | (v[q].y == p3) | (v[q].z == p3) | (v[q].w == p3) |
                    (v[q].x == p4) | (v[q].y == p4) | (v[q].z == p4) | (v[q].w == p4) |
                    (v[q].x == p5) | (v[q].y == p5) | (v[q].z == p5) | (v[q].w == p5);
            }
            if (!hit) continue;   // taken almost never (exact-bit matches only)
            #pragma unroll
            for (int q = 0; q < 4; q++) {
                if (!ok[q]) continue;
                #pragma unroll
                for (int u = 0; u < 4; u++) {
                    unsigned val = (u == 0) ? v[q].x : (u == 1) ? v[q].y
                                 : (u == 2) ? v[q].z : v[q].w;
                    int id = (tt + q * 1024) * 4 + u;
                    #pragma unroll
                    for (int i = 0; i < KCL; i++) {
                        unsigned pp = (i == 0) ? p0 : (i == 1) ? p1 : (i == 2) ? p2
                                    : (i == 3) ? p3 : (i == 4) ? p4 : p5;
                        if (val == pp) {
                            int y = id / H, x = id - y * H;
                            bool cov = false;
                            for (int j = 0; j < i; j++)
                                if ((unsigned)(y - s_wr[j]) < 5u && (unsigned)(x - s_wc[j]) < 5u) cov = true;
                            if (!cov) atomicMin(&s_eq[i], id);
                        }
                    }
                }
            }
        }
    }
    __syncthreads();
    if (tid < KCL) {
        int fh = s_eq[tid];
        s_cy[tid] = (float)(fh / H);
        s_cx[tid] = (float)(fh % H);
    }
    __syncthreads();

    // ---- (III) mean shift
    const int k = warp / RW;            // 0..5 for warps 0..29; warps 30,31 idle
    const int sw = warp - k * RW;
    const bool active = (warp < KCL * RW);

    for (int it = 0; it < ITERS; it++) {
        if (active) {
            float rcy[KCL], rcx[KCL];
            #pragma unroll
            for (int i = 0; i < KCL; i++) { rcy[i] = s_cy[i]; rcx[i] = s_cx[i]; }

            float cy = rcy[0], cx = rcx[0];
            if (k == 1) { cy = rcy[1]; cx = rcx[1]; }
            if (k == 2) { cy = rcy[2]; cx = rcx[2]; }
            if (k == 3) { cy = rcy[3]; cx = rcx[3]; }
            if (k == 4) { cy = rcy[4]; cx = rcx[4]; }
            if (k == 5) { cy = rcy[5]; cx = rcx[5]; }

            const int y0 = max(0, (int)floorf(cy - 12.0f));
            const int y1 = min(H - 1, (int)ceilf(cy + 12.0f));
            const int x0 = max(0, (int)floorf(cx - 12.0f));
            const int x1 = min(H - 1, (int)ceilf(cx + 12.0f));
            const int w  = x1 - x0 + 1;        // <= 26 <= 32 lanes

            float sy = 0.0f, sx = 0.0f, swt = 0.0f;
            const int x = x0 + lane;
            if (lane < w) {
                const float fx = (float)x;
                const float dx2 = (fx - cx) * (fx - cx);
                float ex2[KCL];
                #pragma unroll
                for (int i = 0; i < KCL; i++) {
                    float ex = fx - rcx[i];
                    ex2[i] = ex * ex;
                }
                for (int y = y0 + sw; y <= y1; y += RW) {
                    const float fy = (float)y;
                    const float dy = fy - cy;
                    const float d2r = fmaf(dy, dy, dx2);
                    if (d2r < 144.0f) {
                        float mr = d2r;
                        #pragma unroll
                        for (int k2 = 0; k2 < KCL; k2++) {
                            float ey = fy - rcy[k2];
                            mr = fminf(mr, fmaf(ey, ey, ex2[k2]));
                        }
                        const float d2 = fmaxf(d2r, 1e-6f);
                        const float m2 = fmaxf(mr,  1e-6f);
                        float s = m2 * rsqrtf(m2);               // ~sqrt(m2)
                        float wgt = __fdividef(src[y * H + x] * s, d2);
                        sy = fmaf(wgt, fy, sy);
                        sx = fmaf(wgt, fx, sx);
                        swt += wgt;
                    }
                }
            }
            #pragma unroll
            for (int off = 16; off; off >>= 1) {
                sy  += __shfl_down_sync(0xffffffffu, sy, off);
                sx  += __shfl_down_sync(0xffffffffu, sx, off);
                swt += __shfl_down_sync(0xffffffffu, swt, off);
            }
            if (lane == 0) { pY[k][sw] = sy; pX[k][sw] = sx; pW[k][sw] = swt; }
        }
        __syncthreads();
        // 6 threads update centers (12 MUFU total per iteration)
        if (tid < KCL) {
            float ay = pY[tid][0] + pY[tid][1] + pY[tid][2] + pY[tid][3] + pY[tid][4];
            float ax = pX[tid][0] + pX[tid][1] + pX[tid][2] + pX[tid][3] + pX[tid][4];
            float aw = pW[tid][0] + pW[tid][1] + pW[tid][2] + pW[tid][3] + pW[tid][4];
            s_cy[tid] = __fdividef(ay, aw);
            s_cx[tid] = __fdividef(ax, aw);
        }
        __syncthreads();
    }

    // ---- (IV) outputs
    if (tid < KCL) {
        float fy = s_cy[tid], fx = s_cx[tid];
        int iy = (int)rintf(fy);   // round-half-to-even == jnp.round
        int ix = (int)rintf(fx);
        out[(b * KCL + tid) * 2 + 0] = (float)iy;
        out[(b * KCL + tid) * 2 + 1] = (float)ix;
        int sy0 = min(max(iy - 2, 0), H - 4);   // dynamic_slice clamp
        int sx0 = min(max(ix - 2, 0), H - 4);
        float cf = 0.0f;
        #pragma unroll
        for (int di = 0; di < 4; di++)
            #pragma unroll
            for (int dj = 0; dj < 4; dj++)
                cf += src[(sy0 + di) * H + (sx0 + dj)];
        out[NB * KCL * 2 + b * KCL + tid] = cf;
    }
}

extern "C" void kernel_launch(void* const* d_in, const int* in_sizes, int n_in,
                              void* d_out, int out_size) {
    const float* hm = (const float*)d_in[0];
    float* out = (float*)d_out;

    scan0_kernel<<<dim3(NB, NCH0), 128>>>(hm);
    greedy6_kernel<<<NB, 1024>>>(hm);
    refine_kernel<<<NB, 1024>>>(hm, out);
}

// round 17
// speedup vs baseline: 1.3198x; 1.1427x over previous
#include <cuda_runtime.h>
#include <cuda_bf16.h>

#define H      488
#define AW     484          // H - 5 + 1
#define KCL    6
#define NB     32
#define ITERS  10
#define SEG    121          // 484 = 4 * 121 windows per row
#define NSEG   4
#define NPART  (AW * NSEG)  // 1936 partials per batch
#define CR0    8            // rows per scan0 chunk
#define NCH0   61           // ceil(484/8)
#define NE4    (H * H / 4)  // 59536 uint4/float4 per batch
#define NCHE   8            // eq chunks per batch
#define CE4    7442         // NE4 / 8
#define RW     5            // warps per cluster in refine (30 of 32 warps)

// Scratch (allocation-free: __device__ globals)
__device__ float g_colsum[NB * AW * H];     // vertical 5-sums
__device__ float g_pv[NB * NPART];          // per-(row,seg) argmax value
__device__ int   g_pi[NB * NPART];          // per-(row,seg) argmax flat window idx
__device__ int   g_wr[NB * KCL], g_wc[NB * KCL];
__device__ float g_mv[NB * KCL];
__device__ int   g_eq[NB * KCL];            // first-occurrence flat index

__device__ __forceinline__ void better(float v, int i, float& bv, int& bi) {
    if (v > bv || (v == bv && i < bi)) { bv = v; bi = i; }
}

// ---------------------------------------------------------------------------
// scan0: input -> colsum (global, float4) + initial argmax partials.
// grid (NB, 61) x 128. Partials phase: contiguous window ranges with a
// 5-register ring (1 LDS/window; sum recomputed left-assoc -> bit-exact).
// ---------------------------------------------------------------------------
__global__ __launch_bounds__(128)
void scan0_kernel(const float* __restrict__ in) {
    const int b = blockIdx.x, cb = blockIdx.y, tid = threadIdx.x;
    const float* src = in + (size_t)b * H * H;
    float* cs = g_colsum + (size_t)b * AW * H;

    __shared__ float s_cs[CR0][H];

    const int R0 = CR0 * cb, R1 = min(AW, R0 + CR0);

    // column 5-sums, 4 columns per thread via float4 (left-assoc per column)
    if (tid < H / 4) {
        const float4* s4 = (const float4*)src;
        float4* c4 = (float4*)cs;
        const int HQ = H / 4;                 // 122 float4 per row
        float4 w0 = s4[(R0 + 0) * HQ + tid], w1 = s4[(R0 + 1) * HQ + tid],
               w2 = s4[(R0 + 2) * HQ + tid], w3 = s4[(R0 + 3) * HQ + tid], w4;
        for (int i = R0; i < R1; i++) {
            w4 = s4[(i + 4) * HQ + tid];
            float4 s;
            s.x = w0.x + w1.x + w2.x + w3.x + w4.x;
            s.y = w0.y + w1.y + w2.y + w3.y + w4.y;
            s.z = w0.z + w1.z + w2.z + w3.z + w4.z;
            s.w = w0.w + w1.w + w2.w + w3.w + w4.w;
            *(float4*)&s_cs[i - R0][tid * 4] = s;
            c4[i * HQ + tid] = s;
            w0 = w1; w1 = w2; w2 = w3; w3 = w4;
        }
    }
    __syncthreads();

    // partials: up to 32 (row,seg) pairs, 4 sub-threads each.
    // sub ranges within a 121-window segment: widths {31,30,30,30}.
    const int pair = tid >> 2, sub = tid & 3;
    const int lr = pair >> 2, sg = pair & 3;
    const int nrows = R1 - R0;

    float bv = -1.0f; int bi = 0x7fffffff;
    if (lr < nrows) {
        const float* row = s_cs[lr];
        const int st   = (sub == 0) ? 0 : 31 + 30 * (sub - 1);
        const int wlen = (sub == 0) ? 31 : 30;
        const int j0 = sg * SEG + st;
        float w0 = row[j0], w1 = row[j0 + 1], w2 = row[j0 + 2], w3 = row[j0 + 3], w4;
        for (int j = j0; j < j0 + wlen; j++) {
            w4 = row[j + 4];
            float v = ((((w0 + w1) + w2) + w3) + w4);   // left-assoc, bit-exact
            better(v, (R0 + lr) * AW + j, bv, bi);
            w0 = w1; w1 = w2; w2 = w3; w3 = w4;
        }
    }
    #pragma unroll
    for (int off = 2; off; off >>= 1) {
        float ov = __shfl_down_sync(0xffffffffu, bv, off);
        int   oi = __shfl_down_sync(0xffffffffu, bi, off);
        better(ov, oi, bv, bi);
    }
    if (sub == 0 && lr < nrows) {
        g_pv[b * NPART + (R0 + lr) * NSEG + sg] = bv;
        g_pi[b * NPART + (R0 + lr) * NSEG + sg] = bi;
    }
}

// ---------------------------------------------------------------------------
// greedy6: 6 greedy extractions per batch. grid NB x 512.
// Incremental colsum repair (<=45 entries); lazy D (a partial changes only
// if its stored argmax col is in [c-4, c+4] — sums only decrease).
// ---------------------------------------------------------------------------
__global__ __launch_bounds__(512)
void greedy6_kernel(const float* __restrict__ in) {
    const int b = blockIdx.x, tid = threadIdx.x;
    const int warp = tid >> 5, lane = tid & 31;
    const float* src = in + (size_t)b * H * H;
    float* cs = g_colsum + (size_t)b * AW * H;

    __shared__ float s_pv[NPART];
    __shared__ int   s_pi[NPART];
    __shared__ float s_rv[16];
    __shared__ int   s_ri[16];
    __shared__ int   s_wr[KCL], s_wc[KCL];
    __shared__ float s_mv[KCL];
    __shared__ int   s_r, s_c;

    for (int i = tid; i < NPART; i += 512) {
        s_pv[i] = g_pv[b * NPART + i];
        s_pi[i] = g_pi[b * NPART + i];
    }
    if (tid < KCL) g_eq[b * KCL + tid] = 0x7fffffff;
    __syncthreads();

    for (int it = 0; it < KCL; it++) {
        // A: argmax over 1936 smem partials (two-level shuffle tree)
        {
            float bv = -1.0f; int bi = 0x7fffffff;
            for (int i = tid; i < NPART; i += 512) better(s_pv[i], s_pi[i], bv, bi);
            #pragma unroll
            for (int off = 16; off; off >>= 1) {
                float ov = __shfl_down_sync(0xffffffffu, bv, off);
                int   oi = __shfl_down_sync(0xffffffffu, bi, off);
                better(ov, oi, bv, bi);
            }
            if (lane == 0) { s_rv[warp] = bv; s_ri[warp] = bi; }
        }
        __syncthreads();
        if (warp == 0) {
            float bv = (lane < 16) ? s_rv[lane] : -1.0f;
            int   bi = (lane < 16) ? s_ri[lane] : 0x7fffffff;
            #pragma unroll
            for (int off = 8; off; off >>= 1) {
                float ov = __shfl_down_sync(0xffffffffu, bv, off);
                int   oi = __shfl_down_sync(0xffffffffu, bi, off);
                better(ov, oi, bv, bi);
            }
            if (lane == 0) { s_r = bi / AW; s_c = bi % AW; }
        }
        __syncthreads();
        const int r = s_r, c = s_c;
        const int r0c = max(0, r - 4), r1c = min(AW - 1, r + 4);

        if (warp == 0) {
            // B: window max on warp 0 (value = orig unless covered earlier)
            float v = -1.0f;
            if (lane < 25) {
                int y = r + lane / 5, x = c + lane % 5;
                v = src[y * H + x];
                for (int j = 0; j < it; j++)
                    if ((unsigned)(y - s_wr[j]) < 5u && (unsigned)(x - s_wc[j]) < 5u) v = 0.0f;
            }
            #pragma unroll
            for (int off = 16; off; off >>= 1)
                v = fmaxf(v, __shfl_down_sync(0xffffffffu, v, off));
            if (lane == 0) { s_mv[it] = v; s_wr[it] = r; s_wc[it] = c; }
        } else {
            // C (warps 1+): incremental colsum repair (<=45 entries)
            int nc = (r1c - r0c + 1) * 5;
            int idx = tid - 32;
            if (idx < nc) {
                int rr = r0c + idx / 5, cc = c + idx % 5;
                float s = 0.0f;
                #pragma unroll
                for (int d = 0; d < 5; d++) {
                    int y = rr + d;
                    float v = src[y * H + cc];
                    if ((unsigned)(y - r) < 5u && (unsigned)(cc - c) < 5u) v = 0.0f;
                    for (int j = 0; j < it; j++)
                        if ((unsigned)(y - s_wr[j]) < 5u && (unsigned)(cc - s_wc[j]) < 5u) v = 0.0f;
                    s = s + v;   // left-assoc, matches scan0 ring
                }
                cs[rr * H + cc] = s;
            }
        }
        __syncthreads();

        // D: lazy recompute — only partials whose stored argmax window
        // overlaps the zeroed columns can change (sums only decrease).
        {
            const int jlo = max(0, c - 4), jhi = min(AW - 1, c + 4);
            const int s0 = jlo / SEG, s1 = jhi / SEG;
            const int nsegs = s1 - s0 + 1;
            const int npairs = (r1c - r0c + 1) * nsegs;
            for (int p = warp; p < npairs; p += 16) {
                int rr = r0c + p / nsegs, sg = s0 + p % nsegs;
                int ocol = s_pi[rr * NSEG + sg] - rr * AW;   // argmax window col
                if (ocol < jlo || ocol > jhi) continue;      // provably unchanged
                const float* row = cs + rr * H;
                float bv2 = -1.0f; int bi2 = 0x7fffffff;
                for (int j = sg * SEG + lane; j < sg * SEG + SEG; j += 32) {
                    float v = row[j] + row[j + 1] + row[j + 2] + row[j + 3] + row[j + 4];
                    better(v, rr * AW + j, bv2, bi2);
                }
                #pragma unroll
                for (int off = 16; off; off >>= 1) {
                    float ov = __shfl_down_sync(0xffffffffu, bv2, off);
                    int   oi = __shfl_down_sync(0xffffffffu, bi2, off);
                    better(ov, oi, bv2, bi2);
                }
                if (lane == 0) { s_pv[rr * NSEG + sg] = bv2; s_pi[rr * NSEG + sg] = bi2; }
            }
        }
        __syncthreads();
    }

    if (tid < KCL) {
        g_wr[b * KCL + tid] = s_wr[tid];
        g_wc[b * KCL + tid] = s_wc[tid];
        g_mv[b * KCL + tid] = s_mv[tid];
    }
}

// ---------------------------------------------------------------------------
// eq: first-occurrence scan, grid (NB, 8) x 256 — full chip. Branchless
// exact-bit filter, 4-way unrolled loads for MLP. Global atomicMin.
// ---------------------------------------------------------------------------
__global__ __launch_bounds__(256)
void eq_kernel(const float* __restrict__ in) {
    const int b = blockIdx.x, cb = blockIdx.y, tid = threadIdx.x;

    __shared__ unsigned s_p[KCL];
    __shared__ int      s_wr[KCL], s_wc[KCL];

    if (tid < KCL) {
        s_p[tid]  = __float_as_uint(g_mv[b * KCL + tid]);
        s_wr[tid] = g_wr[b * KCL + tid];
        s_wc[tid] = g_wc[b * KCL + tid];
    }
    __syncthreads();
    const unsigned p0 = s_p[0], p1 = s_p[1], p2 = s_p[2],
                   p3 = s_p[3], p4 = s_p[4], p5 = s_p[5];

    const uint4* h4 = (const uint4*)(in + (size_t)b * H * H);
    const int b0 = cb * CE4, e0 = min(NE4, b0 + CE4);

    for (int tt = b0 + tid; tt < e0; tt += 256 * 4) {
        uint4 v[4];
        bool ok[4];
        #pragma unroll
        for (int q = 0; q < 4; q++) {
            int idx = tt + q * 256;
            ok[q] = idx < e0;
            v[q] = ok[q] ? h4[idx] : make_uint4(0u, 0u, 0u, 0u);
        }
        bool hit = false;
        #pragma unroll
        for (int q = 0; q < 4; q++) {
            hit = hit |
                (v[q].x == p0) | (v[q].y == p0) | (v[q].z == p0) | (v[q].w == p0) |
                (v[q].x == p1) | (v[q].y == p1) | (v[q].z == p1) | (v[q].w == p1) |
                (v[q].x == p2) | (v[q].y == p2) | (v[q].z == p2) | (v[q].w == p2) |
                (v[q].x == p3) | (v[q].y == p3) | (v[q].z == p3) | (v[q].w == p3) |
                (v[q].x == p4) | (v[q].y == p4) | (v[q].z == p4) | (v[q].w == p4) |
                (v[q].x == p5) | (v[q].y == p5) | (v[q].z == p5) | (v[q].w == p5);
        }
        if (!hit) continue;   // taken almost never (exact-bit matches only)
        #pragma unroll
        for (int q = 0; q < 4; q++) {
            if (!ok[q]) continue;
            #pragma unroll
            for (int u = 0; u < 4; u++) {
                unsigned val = (u == 0) ? v[q].x : (u == 1) ? v[q].y
                             : (u == 2) ? v[q].z : v[q].w;
                int id = (tt + q * 256) * 4 + u;
                #pragma unroll
                for (int i = 0; i < KCL; i++) {
                    unsigned pp = (i == 0) ? p0 : (i == 1) ? p1 : (i == 2) ? p2
                                : (i == 3) ? p3 : (i == 4) ? p4 : p5;
                    if (val == pp) {
                        int y = id / H, x = id - y * H;
                        bool cov = false;
                        for (int j = 0; j < i; j++)
                            if ((unsigned)(y - s_wr[j]) < 5u && (unsigned)(x - s_wc[j]) < 5u) cov = true;
                        if (!cov) atomicMin(&g_eq[b * KCL + i], id);
                    }
                }
            }
        }
    }
}

// ---------------------------------------------------------------------------
// refine (R10-proven): 10 mean-shift iterations, 5 warps/cluster, one block
// per batch. rsqrtf + __fdividef, x-invariants hoisted, eps-clamp hoisted
// (exact identity). Centers updated by 6 threads (2 barriers/iter).
// ---------------------------------------------------------------------------
__global__ __launch_bounds__(1024)
void refine_kernel(const float* __restrict__ in, float* __restrict__ out) {
    const int b = blockIdx.x, tid = threadIdx.x;
    const int warp = tid >> 5, lane = tid & 31;
    const float* src = in + (size_t)b * H * H;

    __shared__ float pY[KCL][RW], pX[KCL][RW], pW[KCL][RW];
    __shared__ float s_cy[KCL], s_cx[KCL];

    if (tid < KCL) {
        int fh = g_eq[b * KCL + tid];
        s_cy[tid] = (float)(fh / H);
        s_cx[tid] = (float)(fh % H);
    }
    __syncthreads();

    const int k = warp / RW;            // 0..5 for warps 0..29; warps 30,31 idle
    const int sw = warp - k * RW;
    const bool active = (warp < KCL * RW);

    for (int it = 0; it < ITERS; it++) {
        if (active) {
            float rcy[KCL], rcx[KCL];
            #pragma unroll
            for (int i = 0; i < KCL; i++) { rcy[i] = s_cy[i]; rcx[i] = s_cx[i]; }

            float cy = rcy[0], cx = rcx[0];
            if (k == 1) { cy = rcy[1]; cx = rcx[1]; }
            if (k == 2) { cy = rcy[2]; cx = rcx[2]; }
            if (k == 3) { cy = rcy[3]; cx = rcx[3]; }
            if (k == 4) { cy = rcy[4]; cx = rcx[4]; }
            if (k == 5) { cy = rcy[5]; cx = rcx[5]; }

            const int y0 = max(0, (int)floorf(cy - 12.0f));
            const int y1 = min(H - 1, (int)ceilf(cy + 12.0f));
            const int x0 = max(0, (int)floorf(cx - 12.0f));
            const int x1 = min(H - 1, (int)ceilf(cx + 12.0f));
            const int w  = x1 - x0 + 1;        // <= 26 <= 32 lanes

            float sy = 0.0f, sx = 0.0f, swt = 0.0f;
            const int x = x0 + lane;
            if (lane < w) {
                const float fx = (float)x;
                const float dx2 = (fx - cx) * (fx - cx);
                float ex2[KCL];
                #pragma unroll
                for (int i = 0; i < KCL; i++) {
                    float ex = fx - rcx[i];
                    ex2[i] = ex * ex;
                }
                for (int y = y0 + sw; y <= y1; y += RW) {
                    const float fy = (float)y;
                    const float dy = fy - cy;
                    const float d2r = fmaf(dy, dy, dx2);
                    if (d2r < 144.0f) {
                        float mr = d2r;
                        #pragma unroll
                        for (int k2 = 0; k2 < KCL; k2++) {
                            float ey = fy - rcy[k2];
                            mr = fminf(mr, fmaf(ey, ey, ex2[k2]));
                        }
                        const float d2 = fmaxf(d2r, 1e-6f);
                        const float m2 = fmaxf(mr,  1e-6f);
                        float s = m2 * rsqrtf(m2);               // ~sqrt(m2)
                        float wgt = __fdividef(src[y * H + x] * s, d2);
                        sy = fmaf(wgt, fy, sy);
                        sx = fmaf(wgt, fx, sx);
                        swt += wgt;
                    }
                }
            }
            #pragma unroll
            for (int off = 16; off; off >>= 1) {
                sy  += __shfl_down_sync(0xffffffffu, sy, off);
                sx  += __shfl_down_sync(0xffffffffu, sx, off);
                swt += __shfl_down_sync(0xffffffffu, swt, off);
            }
            if (lane == 0) { pY[k][sw] = sy; pX[k][sw] = sx; pW[k][sw] = swt; }
        }
        __syncthreads();
        // 6 threads update centers (12 MUFU total per iteration)
        if (tid < KCL) {
            float ay = pY[tid][0] + pY[tid][1] + pY[tid][2] + pY[tid][3] + pY[tid][4];
            float ax = pX[tid][0] + pX[tid][1] + pX[tid][2] + pX[tid][3] + pX[tid][4];
            float aw = pW[tid][0] + pW[tid][1] + pW[tid][2] + pW[tid][3] + pW[tid][4];
            s_cy[tid] = __fdividef(ay, aw);
            s_cx[tid] = __fdividef(ax, aw);
        }
        __syncthreads();
    }

    if (tid < KCL) {
        float fy = s_cy[tid], fx = s_cx[tid];
        int iy = (int)rintf(fy);   // round-half-to-even == jnp.round
        int ix = (int)rintf(fx);
        out[(b * KCL + tid) * 2 + 0] = (float)iy;
        out[(b * KCL + tid) * 2 + 1] = (float)ix;
        int sy0 = min(max(iy - 2, 0), H - 4);   // dynamic_slice clamp
        int sx0 = min(max(ix - 2, 0), H - 4);
        float cf = 0.0f;
        #pragma unroll
        for (int di = 0; di < 4; di++)
            #pragma unroll
            for (int dj = 0; dj < 4; dj++)
                cf += src[(sy0 + di) * H + (sx0 + dj)];
        out[NB * KCL * 2 + b * KCL + tid] = cf;
    }
}

extern "C" void kernel_launch(void* const* d_in, const int* in_sizes, int n_in,
                              void* d_out, int out_size) {
    const float* hm = (const float*)d_in[0];
    float* out = (float*)d_out;

    scan0_kernel<<<dim3(NB, NCH0), 128>>>(hm);
    greedy6_kernel<<<NB, 512>>>(hm);
    eq_kernel<<<dim3(NB, NCHE), 256>>>(hm);
    refine_kernel<<<NB, 1024>>>(hm, out);
}